// round 2
// baseline (speedup 1.0000x reference)
#include <cuda_runtime.h>
#include <cuda_bf16.h>
#include <cstddef>

// Problem constants
#define B_   4
#define D_   256
#define E_   512
#define C_   256
#define NEG_INF -1e9f

// Scratch (no cudaMalloc allowed)
__device__ float g_enc_proj[B_ * E_ * C_];   // [b, e, o]
__device__ float g_dec_proj[B_ * D_ * C_];   // [b, d, o]
__device__ float g_scores[B_ * D_ * E_];     // [b, d, e]

__device__ __forceinline__ float tanh_fast(float x) {
    float y;
    asm("tanh.approx.f32 %0, %1;" : "=f"(y) : "f"(x));
    return y;
}

// ---------------------------------------------------------------------------
// GEMM: out[b, r, o] = sum_c X[b, r, c] * W[o, c]   (C = O = 256, R in {512,256})
// 64x64 tile, BK=16, 256 threads, 4x4 micro-tile.
// which = 1 -> g_enc_proj, which = 0 -> g_dec_proj
// ---------------------------------------------------------------------------
__global__ __launch_bounds__(256) void gemm_kernel(const float* __restrict__ X,
                                                   const float* __restrict__ W,
                                                   int R, int which) {
    __shared__ float Xs[64][17];
    __shared__ float Ws[64][17];
    float* out = which ? g_enc_proj : g_dec_proj;

    const int b    = blockIdx.z;
    const int row0 = blockIdx.y * 64;
    const int col0 = blockIdx.x * 64;
    const int t    = threadIdx.x;

    const int lr = t >> 2;           // 0..63
    const int lc = (t & 3) << 2;     // 0,4,8,12
    const int ty = t >> 4;           // 0..15
    const int tx = t & 15;           // 0..15

    const float* Xbase = X + ((size_t)b * R + row0 + lr) * C_;
    const float* Wbase = W + (size_t)(col0 + lr) * C_;

    float acc[4][4];
#pragma unroll
    for (int i = 0; i < 4; i++)
#pragma unroll
        for (int j = 0; j < 4; j++) acc[i][j] = 0.f;

    for (int k0 = 0; k0 < C_; k0 += 16) {
        float4 xa = *(const float4*)(Xbase + k0 + lc);
        float4 wa = *(const float4*)(Wbase + k0 + lc);
        Xs[lr][lc + 0] = xa.x; Xs[lr][lc + 1] = xa.y;
        Xs[lr][lc + 2] = xa.z; Xs[lr][lc + 3] = xa.w;
        Ws[lr][lc + 0] = wa.x; Ws[lr][lc + 1] = wa.y;
        Ws[lr][lc + 2] = wa.z; Ws[lr][lc + 3] = wa.w;
        __syncthreads();
#pragma unroll
        for (int kk = 0; kk < 16; kk++) {
            float a[4], bb[4];
#pragma unroll
            for (int i = 0; i < 4; i++) a[i] = Xs[ty * 4 + i][kk];
#pragma unroll
            for (int j = 0; j < 4; j++) bb[j] = Ws[tx * 4 + j][kk];
#pragma unroll
            for (int i = 0; i < 4; i++)
#pragma unroll
                for (int j = 0; j < 4; j++)
                    acc[i][j] = fmaf(a[i], bb[j], acc[i][j]);
        }
        __syncthreads();
    }

#pragma unroll
    for (int i = 0; i < 4; i++) {
        float4 o4 = make_float4(acc[i][0], acc[i][1], acc[i][2], acc[i][3]);
        *(float4*)(out + ((size_t)b * R + row0 + ty * 4 + i) * C_ + col0 + tx * 4) = o4;
    }
}

// ---------------------------------------------------------------------------
// Scores: s[b,d,e] = sum_c tanh(dec_proj[b,d,c] + enc_proj[b,e,c]) * v[c]
// CTA tile: 16 d x 64 e. 256 threads; thread = (d_loc = t>>4, e_loc = t&15),
// owns 4 e's: e_loc + 16*j. dp/v register-cached in chunks of 8 c.
// ep rows padded to 257 floats -> conflict-free scalar LDS (bank = (e+c)%32).
// ---------------------------------------------------------------------------
#define ETILE 64
#define DTILE 16
#define EPS 257
#define DPS 260
#define SCORES_SMEM ((ETILE * EPS + DTILE * DPS + 256) * 4)

__global__ __launch_bounds__(256, 2) void scores_kernel(const float* __restrict__ v_g) {
    extern __shared__ float sm[];
    float* ep = sm;                       // ETILE * EPS
    float* dp = ep + ETILE * EPS;         // DTILE * DPS
    float* vs = dp + DTILE * DPS;         // 256

    const int b  = blockIdx.z;
    const int d0 = blockIdx.y * DTILE;
    const int e0 = blockIdx.x * ETILE;
    const int t  = threadIdx.x;

    const float* encb = g_enc_proj + ((size_t)b * E_ + e0) * C_;
    for (int i = t; i < ETILE * 64; i += 256) {
        int r = i >> 6, c = (i & 63) << 2;
        float4 x = *(const float4*)(encb + r * C_ + c);
        float* d_ = ep + r * EPS + c;
        d_[0] = x.x; d_[1] = x.y; d_[2] = x.z; d_[3] = x.w;
    }
    const float* decb = g_dec_proj + ((size_t)b * D_ + d0) * C_;
    for (int i = t; i < DTILE * 64; i += 256) {
        int r = i >> 6, c = (i & 63) << 2;
        float4 x = *(const float4*)(decb + r * C_ + c);
        float* d_ = dp + r * DPS + c;
        d_[0] = x.x; d_[1] = x.y; d_[2] = x.z; d_[3] = x.w;
    }
    if (t < 64) ((float4*)vs)[t] = ((const float4*)v_g)[t];
    __syncthreads();

    const int d_loc = t >> 4;
    const int e_loc = t & 15;
    const float* dpr = dp + d_loc * DPS;
    const float* ep0 = ep + e_loc * EPS;

    float acc[4] = {0.f, 0.f, 0.f, 0.f};
    for (int c0 = 0; c0 < C_; c0 += 8) {
        float4 da = *(const float4*)(dpr + c0);
        float4 db = *(const float4*)(dpr + c0 + 4);
        float4 va = *(const float4*)(vs + c0);
        float4 vb = *(const float4*)(vs + c0 + 4);
        float dv[8] = {da.x, da.y, da.z, da.w, db.x, db.y, db.z, db.w};
        float vv[8] = {va.x, va.y, va.z, va.w, vb.x, vb.y, vb.z, vb.w};
#pragma unroll
        for (int j = 0; j < 4; j++) {
            const float* er = ep0 + j * 16 * EPS + c0;
#pragma unroll
            for (int k = 0; k < 8; k++) {
                float tt = tanh_fast(dv[k] + er[k]);
                acc[j] = fmaf(tt, vv[k], acc[j]);
            }
        }
    }

    float* srow = g_scores + ((size_t)b * D_ + d0 + d_loc) * E_ + e0 + e_loc;
#pragma unroll
    for (int j = 0; j < 4; j++) srow[16 * j] = acc[j];
}

// ---------------------------------------------------------------------------
// Masked log-softmax over E=512 per (b,d) row. 128 threads x 4 elems.
// mask is bool promoted to int32 (4 bytes per element, nonzero = keep).
// ---------------------------------------------------------------------------
__global__ __launch_bounds__(128) void softmax_kernel(const int* __restrict__ mask,
                                                      float* __restrict__ out) {
    const int row = blockIdx.x;       // b*D + d
    const int t = threadIdx.x;
    const int wid = t >> 5, lane = t & 31;

    const float* s = g_scores + (size_t)row * E_;
    float4 sv = ((const float4*)s)[t];
    int4 mv = ((const int4*)(mask + (size_t)row * E_))[t];

    float x0 = mv.x ? sv.x : NEG_INF;
    float x1 = mv.y ? sv.y : NEG_INF;
    float x2 = mv.z ? sv.z : NEG_INF;
    float x3 = mv.w ? sv.w : NEG_INF;

    float vmax = fmaxf(fmaxf(x0, x1), fmaxf(x2, x3));
#pragma unroll
    for (int o = 16; o; o >>= 1)
        vmax = fmaxf(vmax, __shfl_xor_sync(0xffffffffu, vmax, o));

    __shared__ float rmax[4], rsum[4];
    if (lane == 0) rmax[wid] = vmax;
    __syncthreads();
    vmax = fmaxf(fmaxf(rmax[0], rmax[1]), fmaxf(rmax[2], rmax[3]));

    float e = expf(x0 - vmax) + expf(x1 - vmax) + expf(x2 - vmax) + expf(x3 - vmax);
#pragma unroll
    for (int o = 16; o; o >>= 1)
        e += __shfl_xor_sync(0xffffffffu, e, o);
    if (lane == 0) rsum[wid] = e;
    __syncthreads();
    float tot = rsum[0] + rsum[1] + rsum[2] + rsum[3];
    float lse = vmax + logf(tot);

    float4 o4 = make_float4(x0 - lse, x1 - lse, x2 - lse, x3 - lse);
    ((float4*)(out + (size_t)row * E_))[t] = o4;
}

// ---------------------------------------------------------------------------
extern "C" void kernel_launch(void* const* d_in, const int* in_sizes, int n_in,
                              void* d_out, int out_size) {
    const float* decoder = (const float*)d_in[0];
    const float* encoder = (const float*)d_in[1];
    const int*   mask    = (const int*)d_in[2];
    const float* W1      = (const float*)d_in[3];
    const float* W2      = (const float*)d_in[4];
    const float* v       = (const float*)d_in[5];
    float* out           = (float*)d_out;

    cudaFuncSetAttribute(scores_kernel,
                         cudaFuncAttributeMaxDynamicSharedMemorySize, SCORES_SMEM);

    // encoder_proj = encoder @ W1^T  : R = E_ = 512
    gemm_kernel<<<dim3(C_ / 64, E_ / 64, B_), 256>>>(encoder, W1, E_, 1);
    // decoder_proj = decoder @ W2^T  : R = D_ = 256
    gemm_kernel<<<dim3(C_ / 64, D_ / 64, B_), 256>>>(decoder, W2, D_, 0);
    // scores
    scores_kernel<<<dim3(E_ / ETILE, D_ / DTILE, B_), 256, SCORES_SMEM>>>(v);
    // masked log-softmax
    softmax_kernel<<<B_ * D_, 128>>>(mask, out);
}

// round 3
// speedup vs baseline: 1.0358x; 1.0358x over previous
#include <cuda_runtime.h>
#include <cuda_bf16.h>
#include <cstddef>

// Problem constants
#define B_   4
#define D_   256
#define E_   512
#define C_   256
#define NEG_INF -1e9f

// Scratch (no cudaMalloc allowed)
__device__ float g_enc_proj[B_ * E_ * C_];   // [b, e, o]
__device__ float g_dec_proj[B_ * D_ * C_];   // [b, d, o]
__device__ float g_scores[B_ * D_ * E_];     // [b, d, e]

// tanh of a pair via one MUFU f16x2 op. a,b packed to f16, tanh'd, unpacked.
__device__ __forceinline__ void tanh2_fast(float a, float b, float& ta, float& tb) {
    unsigned int h2, t2;
    asm("cvt.rn.f16x2.f32 %0, %1, %2;" : "=r"(h2) : "f"(b), "f"(a)); // lo=a, hi=b
    asm("tanh.approx.f16x2 %0, %1;" : "=r"(t2) : "r"(h2));
    asm("{\n\t"
        ".reg .f16 l, h;\n\t"
        "mov.b32 {l, h}, %2;\n\t"
        "cvt.f32.f16 %0, l;\n\t"
        "cvt.f32.f16 %1, h;\n\t"
        "}" : "=f"(ta), "=f"(tb) : "r"(t2));
}

// ---------------------------------------------------------------------------
// Fused GEMM: both projections in one launch.
//   blockIdx.y < 8 : enc_proj tile (R = 512), else dec_proj tile (R = 256).
// out[b, r, o] = sum_c X[b, r, c] * W[o, c].  64x64 tile, BK=16, 4x4 micro.
// ---------------------------------------------------------------------------
__global__ __launch_bounds__(256) void gemm_fused_kernel(
        const float* __restrict__ enc, const float* __restrict__ dec,
        const float* __restrict__ W1,  const float* __restrict__ W2) {
    __shared__ float Xs[64][17];
    __shared__ float Ws[64][17];

    const int b  = blockIdx.z;
    const int yt = blockIdx.y;
    const bool is_enc = (yt < 8);
    const int R      = is_enc ? E_ : D_;
    const int row0   = (is_enc ? yt : yt - 8) * 64;
    const int col0   = blockIdx.x * 64;
    const float* X   = is_enc ? enc : dec;
    const float* W   = is_enc ? W1  : W2;
    float* out       = is_enc ? g_enc_proj : g_dec_proj;

    const int t  = threadIdx.x;
    const int lr = t >> 2;           // 0..63
    const int lc = (t & 3) << 2;     // 0,4,8,12
    const int ty = t >> 4;           // 0..15
    const int tx = t & 15;           // 0..15

    const float* Xbase = X + ((size_t)b * R + row0 + lr) * C_;
    const float* Wbase = W + (size_t)(col0 + lr) * C_;

    float acc[4][4];
#pragma unroll
    for (int i = 0; i < 4; i++)
#pragma unroll
        for (int j = 0; j < 4; j++) acc[i][j] = 0.f;

    for (int k0 = 0; k0 < C_; k0 += 16) {
        float4 xa = *(const float4*)(Xbase + k0 + lc);
        float4 wa = *(const float4*)(Wbase + k0 + lc);
        Xs[lr][lc + 0] = xa.x; Xs[lr][lc + 1] = xa.y;
        Xs[lr][lc + 2] = xa.z; Xs[lr][lc + 3] = xa.w;
        Ws[lr][lc + 0] = wa.x; Ws[lr][lc + 1] = wa.y;
        Ws[lr][lc + 2] = wa.z; Ws[lr][lc + 3] = wa.w;
        __syncthreads();
#pragma unroll
        for (int kk = 0; kk < 16; kk++) {
            float a[4], bb[4];
#pragma unroll
            for (int i = 0; i < 4; i++) a[i] = Xs[ty * 4 + i][kk];
#pragma unroll
            for (int j = 0; j < 4; j++) bb[j] = Ws[tx * 4 + j][kk];
#pragma unroll
            for (int i = 0; i < 4; i++)
#pragma unroll
                for (int j = 0; j < 4; j++)
                    acc[i][j] = fmaf(a[i], bb[j], acc[i][j]);
        }
        __syncthreads();
    }

#pragma unroll
    for (int i = 0; i < 4; i++) {
        float4 o4 = make_float4(acc[i][0], acc[i][1], acc[i][2], acc[i][3]);
        *(float4*)(out + ((size_t)b * R + row0 + ty * 4 + i) * C_ + col0 + tx * 4) = o4;
    }
}

// ---------------------------------------------------------------------------
// Scores: s[b,d,e] = sum_c tanh(dec_proj[b,d,c] + enc_proj[b,e,c]) * v[c]
// CTA tile: 16 d x 64 e. 256 threads; thread = (d_loc = t>>4, e_loc = t&15),
// owns 4 e's: e_loc + 16*j. dp/v register-cached in chunks of 8 c.
// tanh done pairwise through the f16x2 MUFU path (2 elems / MUFU op).
// ---------------------------------------------------------------------------
#define ETILE 64
#define DTILE 16
#define EPS 257
#define DPS 260
#define SCORES_SMEM ((ETILE * EPS + DTILE * DPS + 256) * 4)

__global__ __launch_bounds__(256, 2) void scores_kernel(const float* __restrict__ v_g) {
    extern __shared__ float sm[];
    float* ep = sm;                       // ETILE * EPS
    float* dp = ep + ETILE * EPS;         // DTILE * DPS
    float* vs = dp + DTILE * DPS;         // 256

    const int b  = blockIdx.z;
    const int d0 = blockIdx.y * DTILE;
    const int e0 = blockIdx.x * ETILE;
    const int t  = threadIdx.x;

    const float* encb = g_enc_proj + ((size_t)b * E_ + e0) * C_;
    for (int i = t; i < ETILE * 64; i += 256) {
        int r = i >> 6, c = (i & 63) << 2;
        float4 x = *(const float4*)(encb + r * C_ + c);
        float* d_ = ep + r * EPS + c;
        d_[0] = x.x; d_[1] = x.y; d_[2] = x.z; d_[3] = x.w;
    }
    const float* decb = g_dec_proj + ((size_t)b * D_ + d0) * C_;
    for (int i = t; i < DTILE * 64; i += 256) {
        int r = i >> 6, c = (i & 63) << 2;
        float4 x = *(const float4*)(decb + r * C_ + c);
        float* d_ = dp + r * DPS + c;
        d_[0] = x.x; d_[1] = x.y; d_[2] = x.z; d_[3] = x.w;
    }
    if (t < 64) ((float4*)vs)[t] = ((const float4*)v_g)[t];
    __syncthreads();

    const int d_loc = t >> 4;
    const int e_loc = t & 15;
    const float* dpr = dp + d_loc * DPS;
    const float* ep0 = ep + e_loc * EPS;

    float acc[4] = {0.f, 0.f, 0.f, 0.f};
    for (int c0 = 0; c0 < C_; c0 += 8) {
        float4 da = *(const float4*)(dpr + c0);
        float4 db = *(const float4*)(dpr + c0 + 4);
        float4 va = *(const float4*)(vs + c0);
        float4 vb = *(const float4*)(vs + c0 + 4);
        float dv[8] = {da.x, da.y, da.z, da.w, db.x, db.y, db.z, db.w};
        float vv[8] = {va.x, va.y, va.z, va.w, vb.x, vb.y, vb.z, vb.w};
#pragma unroll
        for (int j = 0; j < 4; j++) {
            const float* er = ep0 + j * 16 * EPS + c0;
#pragma unroll
            for (int kp = 0; kp < 4; kp++) {
                float s0 = dv[2 * kp]     + er[2 * kp];
                float s1 = dv[2 * kp + 1] + er[2 * kp + 1];
                float t0, t1;
                tanh2_fast(s0, s1, t0, t1);
                acc[j] = fmaf(t0, vv[2 * kp],     acc[j]);
                acc[j] = fmaf(t1, vv[2 * kp + 1], acc[j]);
            }
        }
    }

    float* srow = g_scores + ((size_t)b * D_ + d0 + d_loc) * E_ + e0 + e_loc;
#pragma unroll
    for (int j = 0; j < 4; j++) srow[16 * j] = acc[j];
}

// ---------------------------------------------------------------------------
// Masked log-softmax over E=512 per (b,d) row. 128 threads x 4 elems.
// mask is bool promoted to int32 (4 bytes per element, nonzero = keep).
// ---------------------------------------------------------------------------
__global__ __launch_bounds__(128) void softmax_kernel(const int* __restrict__ mask,
                                                      float* __restrict__ out) {
    const int row = blockIdx.x;       // b*D + d
    const int t = threadIdx.x;
    const int wid = t >> 5, lane = t & 31;

    const float* s = g_scores + (size_t)row * E_;
    float4 sv = ((const float4*)s)[t];
    int4 mv = ((const int4*)(mask + (size_t)row * E_))[t];

    float x0 = mv.x ? sv.x : NEG_INF;
    float x1 = mv.y ? sv.y : NEG_INF;
    float x2 = mv.z ? sv.z : NEG_INF;
    float x3 = mv.w ? sv.w : NEG_INF;

    float vmax = fmaxf(fmaxf(x0, x1), fmaxf(x2, x3));
#pragma unroll
    for (int o = 16; o; o >>= 1)
        vmax = fmaxf(vmax, __shfl_xor_sync(0xffffffffu, vmax, o));

    __shared__ float rmax[4], rsum[4];
    if (lane == 0) rmax[wid] = vmax;
    __syncthreads();
    vmax = fmaxf(fmaxf(rmax[0], rmax[1]), fmaxf(rmax[2], rmax[3]));

    float e = expf(x0 - vmax) + expf(x1 - vmax) + expf(x2 - vmax) + expf(x3 - vmax);
#pragma unroll
    for (int o = 16; o; o >>= 1)
        e += __shfl_xor_sync(0xffffffffu, e, o);
    if (lane == 0) rsum[wid] = e;
    __syncthreads();
    float tot = rsum[0] + rsum[1] + rsum[2] + rsum[3];
    float lse = vmax + logf(tot);

    float4 o4 = make_float4(x0 - lse, x1 - lse, x2 - lse, x3 - lse);
    ((float4*)(out + (size_t)row * E_))[t] = o4;
}

// ---------------------------------------------------------------------------
extern "C" void kernel_launch(void* const* d_in, const int* in_sizes, int n_in,
                              void* d_out, int out_size) {
    const float* decoder = (const float*)d_in[0];
    const float* encoder = (const float*)d_in[1];
    const int*   mask    = (const int*)d_in[2];
    const float* W1      = (const float*)d_in[3];
    const float* W2      = (const float*)d_in[4];
    const float* v       = (const float*)d_in[5];
    float* out           = (float*)d_out;

    cudaFuncSetAttribute(scores_kernel,
                         cudaFuncAttributeMaxDynamicSharedMemorySize, SCORES_SMEM);

    // Both projections in one wave: y tiles [0,8) -> enc (R=512), [8,12) -> dec (R=256)
    gemm_fused_kernel<<<dim3(C_ / 64, 12, B_), 256>>>(encoder, decoder, W1, W2);
    // scores
    scores_kernel<<<dim3(E_ / ETILE, D_ / DTILE, B_), 256, SCORES_SMEM>>>(v);
    // masked log-softmax
    softmax_kernel<<<B_ * D_, 128>>>(mask, out);
}

// round 5
// speedup vs baseline: 1.2133x; 1.1714x over previous
#include <cuda_runtime.h>
#include <cuda_fp16.h>
#include <cuda_bf16.h>
#include <cstddef>

// Problem constants
#define B_   4
#define D_   256
#define E_   512
#define C_   256
#define NEG_INF -1e9f

// Scratch (no cudaMalloc allowed)
__device__ __half g_enc_proj[B_ * E_ * C_];   // [b, e, o] half
__device__ __half g_dec_proj[B_ * D_ * C_];   // [b, d, o] half
__device__ float  g_scores[B_ * D_ * E_];     // [b, d, e]

__device__ __forceinline__ __half2 tanh2h(__half2 x) {
    unsigned int r, xi = *reinterpret_cast<unsigned int*>(&x);
    asm("tanh.approx.f16x2 %0, %1;" : "=r"(r) : "r"(xi));
    return *reinterpret_cast<__half2*>(&r);
}
__device__ __forceinline__ __half2 u2h(unsigned int u) {
    return *reinterpret_cast<__half2*>(&u);
}

// ---------------------------------------------------------------------------
// Fused GEMM: out[b,r,o] = sum_c X[b,r,c] * W[o,c], output stored as half.
// Tile 64 rows x 32 cols, BK=16, 128 threads, 4x4 micro-tile.
// Transposed smem (Xs[kk][row]) -> inner loop = 2x LDS.128 + 16 FFMA.
// grid: x = 8 col tiles, y = 12 row tiles (0..7 enc R=512, 8..11 dec R=256), z = B.
// ---------------------------------------------------------------------------
__global__ __launch_bounds__(128) void gemm_fused_kernel(
        const float* __restrict__ enc, const float* __restrict__ dec,
        const float* __restrict__ W1,  const float* __restrict__ W2) {
    __shared__ float Xs[16][68];
    __shared__ float Ws[16][36];

    const int b  = blockIdx.z;
    const int yt = blockIdx.y;
    const bool is_enc = (yt < 8);
    const int R      = is_enc ? E_ : D_;
    const int row0   = (is_enc ? yt : yt - 8) * 64;
    const int col0   = blockIdx.x * 32;
    const float* X   = is_enc ? enc : dec;
    const float* W   = is_enc ? W1  : W2;
    __half* out      = is_enc ? g_enc_proj : g_dec_proj;

    const int t  = threadIdx.x;
    const int lr = t >> 2;           // 0..31
    const int lc = (t & 3) << 2;     // 0,4,8,12
    const int ty = t >> 3;           // 0..15 (row group)
    const int tx = t & 7;            // 0..7  (col group)

    const float* Xb = X + ((size_t)b * R + row0 + lr) * C_ + lc;
    const float* Wb = W + (size_t)(col0 + lr) * C_ + lc;

    float4 xa0 = *(const float4*)Xb;
    float4 xa1 = *(const float4*)(Xb + 32 * C_);
    float4 wa  = *(const float4*)Wb;

    float acc[4][4];
#pragma unroll
    for (int i = 0; i < 4; i++)
#pragma unroll
        for (int j = 0; j < 4; j++) acc[i][j] = 0.f;

    for (int k0 = 0; k0 < C_; k0 += 16) {
        Xs[lc + 0][lr] = xa0.x; Xs[lc + 1][lr] = xa0.y;
        Xs[lc + 2][lr] = xa0.z; Xs[lc + 3][lr] = xa0.w;
        Xs[lc + 0][lr + 32] = xa1.x; Xs[lc + 1][lr + 32] = xa1.y;
        Xs[lc + 2][lr + 32] = xa1.z; Xs[lc + 3][lr + 32] = xa1.w;
        Ws[lc + 0][lr] = wa.x; Ws[lc + 1][lr] = wa.y;
        Ws[lc + 2][lr] = wa.z; Ws[lc + 3][lr] = wa.w;
        __syncthreads();
        if (k0 + 16 < C_) {
            xa0 = *(const float4*)(Xb + k0 + 16);
            xa1 = *(const float4*)(Xb + 32 * C_ + k0 + 16);
            wa  = *(const float4*)(Wb + k0 + 16);
        }
#pragma unroll
        for (int kk = 0; kk < 16; kk++) {
            float4 a4 = *(const float4*)&Xs[kk][ty * 4];
            float4 b4 = *(const float4*)&Ws[kk][tx * 4];
            float a[4] = {a4.x, a4.y, a4.z, a4.w};
            float bb[4] = {b4.x, b4.y, b4.z, b4.w};
#pragma unroll
            for (int i = 0; i < 4; i++)
#pragma unroll
                for (int j = 0; j < 4; j++)
                    acc[i][j] = fmaf(a[i], bb[j], acc[i][j]);
        }
        __syncthreads();
    }

#pragma unroll
    for (int i = 0; i < 4; i++) {
        __half2 h0 = __floats2half2_rn(acc[i][0], acc[i][1]);
        __half2 h1 = __floats2half2_rn(acc[i][2], acc[i][3]);
        uint2 pk = make_uint2(*reinterpret_cast<unsigned int*>(&h0),
                              *reinterpret_cast<unsigned int*>(&h1));
        *(uint2*)(out + ((size_t)b * R + row0 + ty * 4 + i) * C_ + col0 + tx * 4) = pk;
    }
}

// ---------------------------------------------------------------------------
// Scores: s[b,d,e] = sum_c tanh(dec_proj[b,d,c] + enc_proj[b,e,c]) * v[c]
// Fully half2 SIMD: HADD2 + tanh.approx.f16x2 + HFMA2, flush to fp32 /32 c.
// CTA tile: 16 d x 64 e, 256 threads; thread (d_loc=t>>4, e_loc=t&15) does
// 4 e's (e_loc + 16j). ep pitch 130 uint (conflict-free LDS.64),
// dp pitch 132 (16B aligned LDS.128, broadcast).
// ---------------------------------------------------------------------------
#define ETILE 64
#define DTILE 16
#define EP_P 130
#define DP_P 132
#define SCORES_SMEM ((ETILE * EP_P + DTILE * DP_P + 128) * 4)

__global__ __launch_bounds__(256) void scores_kernel(const float* __restrict__ v_g) {
    extern __shared__ unsigned int smu[];
    unsigned int* ep  = smu;                        // ETILE * EP_P half2
    unsigned int* dpu = ep + ETILE * EP_P;          // DTILE * DP_P half2
    unsigned int* vsu = dpu + DTILE * DP_P;         // 128 half2

    const int b  = blockIdx.z;
    const int d0 = blockIdx.y * DTILE;
    const int e0 = blockIdx.x * ETILE;
    const int t  = threadIdx.x;

    // Fill ep: 64 rows, each row = 256 halves = 32 uint4
    const __half* encb = g_enc_proj + ((size_t)b * E_ + e0) * C_;
    for (int i = t; i < ETILE * 32; i += 256) {
        int r = i >> 5, q = i & 31;
        uint4 s = ((const uint4*)encb)[r * 32 + q];
        unsigned int* dst = ep + r * EP_P + q * 4;
        dst[0] = s.x; dst[1] = s.y; dst[2] = s.z; dst[3] = s.w;
    }
    // Fill dp: 16 rows x 32 uint4
    const __half* decb = g_dec_proj + ((size_t)b * D_ + d0) * C_;
    for (int i = t; i < DTILE * 32; i += 256) {
        int r = i >> 5, q = i & 31;
        uint4 s = ((const uint4*)decb)[r * 32 + q];
        *(uint4*)(dpu + r * DP_P + q * 4) = s;
    }
    // Fill v as half2
    if (t < 128) {
        float2 vf = ((const float2*)v_g)[t];
        __half2 vh = __floats2half2_rn(vf.x, vf.y);
        vsu[t] = *reinterpret_cast<unsigned int*>(&vh);
    }
    __syncthreads();

    const int d_loc = t >> 4;
    const int e_loc = t & 15;
    const unsigned int* dpr = dpu + d_loc * DP_P;
    const unsigned int* epr = ep + e_loc * EP_P;

    __half2 a2[4];
    float facc[4] = {0.f, 0.f, 0.f, 0.f};
#pragma unroll
    for (int j = 0; j < 4; j++) a2[j] = __floats2half2_rn(0.f, 0.f);

    for (int c8 = 0; c8 < 128; c8 += 4) {      // 4 half2 = 8 c per chunk
        uint4 du = *(const uint4*)(dpr + c8);
        uint4 vu = *(const uint4*)(vsu + c8);
        __half2 dv0 = u2h(du.x), dv1 = u2h(du.y), dv2 = u2h(du.z), dv3 = u2h(du.w);
        __half2 vv0 = u2h(vu.x), vv1 = u2h(vu.y), vv2 = u2h(vu.z), vv3 = u2h(vu.w);
#pragma unroll
        for (int j = 0; j < 4; j++) {
            const unsigned int* er = epr + j * (16 * EP_P) + c8;
            uint2 e01 = *(const uint2*)er;
            uint2 e23 = *(const uint2*)(er + 2);
            a2[j] = __hfma2(tanh2h(__hadd2(dv0, u2h(e01.x))), vv0, a2[j]);
            a2[j] = __hfma2(tanh2h(__hadd2(dv1, u2h(e01.y))), vv1, a2[j]);
            a2[j] = __hfma2(tanh2h(__hadd2(dv2, u2h(e23.x))), vv2, a2[j]);
            a2[j] = __hfma2(tanh2h(__hadd2(dv3, u2h(e23.y))), vv3, a2[j]);
        }
        if ((c8 & 12) == 12) {                  // flush every 32 c's
#pragma unroll
            for (int j = 0; j < 4; j++) {
                float2 f = __half22float2(a2[j]);
                facc[j] += f.x + f.y;
                a2[j] = __floats2half2_rn(0.f, 0.f);
            }
        }
    }

    float* srow = g_scores + ((size_t)b * D_ + d0 + d_loc) * E_ + e0 + e_loc;
#pragma unroll
    for (int j = 0; j < 4; j++) srow[16 * j] = facc[j];
}

// ---------------------------------------------------------------------------
// Masked log-softmax over E=512 per (b,d) row. 128 threads x 4 elems.
// mask is bool promoted to int32 (4 bytes per element, nonzero = keep).
// ---------------------------------------------------------------------------
__global__ __launch_bounds__(128) void softmax_kernel(const int* __restrict__ mask,
                                                      float* __restrict__ out) {
    const int row = blockIdx.x;       // b*D + d
    const int t = threadIdx.x;
    const int wid = t >> 5, lane = t & 31;

    const float* s = g_scores + (size_t)row * E_;
    float4 sv = ((const float4*)s)[t];
    int4 mv = ((const int4*)(mask + (size_t)row * E_))[t];

    float x0 = mv.x ? sv.x : NEG_INF;
    float x1 = mv.y ? sv.y : NEG_INF;
    float x2 = mv.z ? sv.z : NEG_INF;
    float x3 = mv.w ? sv.w : NEG_INF;

    float vmax = fmaxf(fmaxf(x0, x1), fmaxf(x2, x3));
#pragma unroll
    for (int o = 16; o; o >>= 1)
        vmax = fmaxf(vmax, __shfl_xor_sync(0xffffffffu, vmax, o));

    __shared__ float rmax[4], rsum[4];
    if (lane == 0) rmax[wid] = vmax;
    __syncthreads();
    vmax = fmaxf(fmaxf(rmax[0], rmax[1]), fmaxf(rmax[2], rmax[3]));

    float e = expf(x0 - vmax) + expf(x1 - vmax) + expf(x2 - vmax) + expf(x3 - vmax);
#pragma unroll
    for (int o = 16; o; o >>= 1)
        e += __shfl_xor_sync(0xffffffffu, e, o);
    if (lane == 0) rsum[wid] = e;
    __syncthreads();
    float tot = rsum[0] + rsum[1] + rsum[2] + rsum[3];
    float lse = vmax + logf(tot);

    float4 o4 = make_float4(x0 - lse, x1 - lse, x2 - lse, x3 - lse);
    ((float4*)(out + (size_t)row * E_))[t] = o4;
}

// ---------------------------------------------------------------------------
extern "C" void kernel_launch(void* const* d_in, const int* in_sizes, int n_in,
                              void* d_out, int out_size) {
    const float* decoder = (const float*)d_in[0];
    const float* encoder = (const float*)d_in[1];
    const int*   mask    = (const int*)d_in[2];
    const float* W1      = (const float*)d_in[3];
    const float* W2      = (const float*)d_in[4];
    const float* v       = (const float*)d_in[5];
    float* out           = (float*)d_out;

    cudaFuncSetAttribute(scores_kernel,
                         cudaFuncAttributeMaxDynamicSharedMemorySize, SCORES_SMEM);

    // Both projections: y tiles [0,8) -> enc (R=512), [8,12) -> dec (R=256)
    gemm_fused_kernel<<<dim3(8, 12, B_), 128>>>(encoder, decoder, W1, W2);
    // scores (fully half2 SIMD path)
    scores_kernel<<<dim3(E_ / ETILE, D_ / DTILE, B_), 256, SCORES_SMEM>>>(v);
    // masked log-softmax
    softmax_kernel<<<B_ * D_, 128>>>(mask, out);
}